// round 1
// baseline (speedup 1.0000x reference)
#include <cuda_runtime.h>
#include <math.h>

#define HW 65536
#define C_ 64
#define R_ 8
#define B_ 4

// ---------------- device scratch (no allocations allowed) ----------------
__device__ float d_partial[16][16];                    // [plane=(b*4+i)][chunk]
__device__ float d_t[B_][64];                          // sigmoid activations
__device__ __align__(16) float d_kp4[B_][R_][C_][4];   // folded kernel @ W1
__device__ float d_kb[B_][R_][C_];                     // folded kernel @ b1
__device__ __align__(16) float d_wgp[R_][4];           // Wg @ W1
__device__ float d_bgp[R_];                            // Wg @ b1 + bg

// ---------------- 1) per-plane partial sums (for global means) ----------------
__global__ void reduce_kernel(const float* __restrict__ rgb, const float* __restrict__ edge) {
    int plane = blockIdx.y;             // 0..15  -> b = plane>>2, i = plane&3
    int b = plane >> 2, i = plane & 3;
    const float* src = (i < 3) ? (rgb + (size_t)(b * 3 + i) * HW)
                               : (edge + (size_t)b * HW);
    const float4* p = (const float4*)src + blockIdx.x * 1024;   // 16 chunks of 4096 floats
    int tid = threadIdx.x;              // 256 threads
    float s = 0.f;
#pragma unroll
    for (int k = 0; k < 4; k++) {
        float4 v = p[tid + k * 256];
        s += (v.x + v.y) + (v.z + v.w);
    }
#pragma unroll
    for (int off = 16; off; off >>= 1) s += __shfl_down_sync(0xFFFFFFFFu, s, off);
    __shared__ float ws[8];
    if ((tid & 31) == 0) ws[tid >> 5] = s;
    __syncthreads();
    if (tid < 8) {
        float v = ws[tid];
#pragma unroll
        for (int off = 4; off; off >>= 1) v += __shfl_down_sync(0xFFu, v, off);
        if (tid == 0) d_partial[plane][blockIdx.x] = v;
    }
}

// ---------------- 2) g -> t = sigmoid(...), plus folded guide weights ----------------
__global__ void gent_kernel(const float* __restrict__ W1, const float* __restrict__ b1,
                            const float* __restrict__ Wk1, const float* __restrict__ bk1,
                            const float* __restrict__ Wg, const float* __restrict__ bg) {
    int b = blockIdx.x, tid = threadIdx.x;   // 64 threads
    __shared__ float m4[4], g[64];
    if (tid < 4) {
        float s = 0.f;
#pragma unroll
        for (int ch = 0; ch < 16; ch++) s += d_partial[b * 4 + tid][ch];
        m4[tid] = s * (1.0f / 65536.0f);
    }
    __syncthreads();
    g[tid] = b1[tid] + W1[tid * 4 + 0] * m4[0] + W1[tid * 4 + 1] * m4[1]
                     + W1[tid * 4 + 2] * m4[2] + W1[tid * 4 + 3] * m4[3];
    __syncthreads();
    float a = bk1[tid];
#pragma unroll 8
    for (int c = 0; c < 64; c++) a += Wk1[tid * 64 + c] * g[c];
    d_t[b][tid] = 1.f / (1.f + expf(-a));

    if (b == 0) {  // folded guide weights: Wg@W1 (8x4), Wg@b1+bg (8)
        if (tid < 32) {
            int r = tid >> 2, j = tid & 3;
            float s = 0.f;
            for (int c = 0; c < 64; c++) s += Wg[r * 64 + c] * W1[c * 4 + j];
            d_wgp[r][j] = s;
        } else if (tid < 40) {
            int r = tid - 32;
            float s = bg[r];
            for (int c = 0; c < 64; c++) s += Wg[r * 64 + c] * b1[c];
            d_bgp[r] = s;
        }
    }
}

// ---------------- 3) generated kernels, folded through W1/b1 ----------------
__global__ void genk_kernel(const float* __restrict__ Wk2, const float* __restrict__ bk2,
                            const float* __restrict__ W1, const float* __restrict__ b1) {
    __shared__ float kern[4096];                     // kernel[b][r][co*64+ci]
    int b = blockIdx.x >> 3, r = blockIdx.x & 7;     // 32 blocks
    int tid = threadIdx.x;                           // 256 threads
    float tg[8];
#pragma unroll
    for (int i = 0; i < 8; i++) tg[i] = d_t[b][r * 8 + i];
    const float* w2 = Wk2 + (size_t)r * 4096 * 8;
    const float* bk = bk2 + r * 4096;
    for (int o = tid; o < 4096; o += 256) {
        float a = bk[o];
#pragma unroll
        for (int i = 0; i < 8; i++) a += tg[i] * w2[o * 8 + i];
        kern[o] = a;
    }
    __syncthreads();
    int c = tid >> 2, j = tid & 3;                   // 64 x 4 threads
    float acc = 0.f;
#pragma unroll 8
    for (int ci = 0; ci < 64; ci++) acc += kern[c * 64 + ci] * W1[ci * 4 + j];
    d_kp4[b][r][c][j] = acc;
    if (j == 0) {
        float ab = 0.f;
#pragma unroll 8
        for (int ci = 0; ci < 64; ci++) ab += kern[c * 64 + ci] * b1[ci];
        d_kb[b][r][c] = ab;
    }
}

// ---------------- 4) streaming main pass: guide argmax + 64x5 matvec ----------------
__global__ void __launch_bounds__(128) main_kernel(const float* __restrict__ rgb,
                                                   const float* __restrict__ edge,
                                                   float* __restrict__ out) {
    // padded stride 65: LDS.128 start bank = (4r + 4c) mod 32 -> disjoint per region
    __shared__ float4 skp[R_][C_ + 1];
    __shared__ float  skb[R_][C_ + 1];
    int tid = threadIdx.x;
    int b = blockIdx.y;

    const float4* kps = (const float4*)&d_kp4[b][0][0][0];
    for (int idx = tid; idx < R_ * C_; idx += 128) skp[idx >> 6][idx & 63] = kps[idx];
    const float* kbs = &d_kb[b][0][0];
    for (int idx = tid; idx < R_ * C_; idx += 128) skb[idx >> 6][idx & 63] = kbs[idx];

    float4 wg[8]; float bgr[8];
#pragma unroll
    for (int r = 0; r < 8; r++) {
        wg[r] = *(const float4*)d_wgp[r];
        bgr[r] = d_bgp[r];
    }
    __syncthreads();

    int pb = blockIdx.x * 512 + tid * 4;   // 4 consecutive pixels per thread
    const float* base = rgb + (size_t)b * 3 * HW;
    float4 c0 = *(const float4*)(base + pb);
    float4 c1 = *(const float4*)(base + HW + pb);
    float4 c2 = *(const float4*)(base + 2 * HW + pb);
    float4 c3 = *(const float4*)(edge + (size_t)b * HW + pb);
    float xs0[4] = {c0.x, c0.y, c0.z, c0.w};
    float xs1[4] = {c1.x, c1.y, c1.z, c1.w};
    float xs2[4] = {c2.x, c2.y, c2.z, c2.w};
    float xs3[4] = {c3.x, c3.y, c3.z, c3.w};

    int rsel[4];
#pragma unroll
    for (int j = 0; j < 4; j++) {
        float best = -3.4e38f; int ri = 0;
#pragma unroll
        for (int r = 0; r < 8; r++) {
            float gv = bgr[r] + wg[r].x * xs0[j] + wg[r].y * xs1[j]
                              + wg[r].z * xs2[j] + wg[r].w * xs3[j];
            if (gv > best) { best = gv; ri = r; }   // strict > keeps first max (jnp.argmax)
        }
        rsel[j] = ri;
    }

    float* op = out + (size_t)b * 64 * HW + pb;
#pragma unroll 8
    for (int c = 0; c < 64; c++) {
        float acc[4];
#pragma unroll
        for (int j = 0; j < 4; j++) {
            float4 w = skp[rsel[j]][c];
            acc[j] = skb[rsel[j]][c] + w.x * xs0[j] + w.y * xs1[j]
                                     + w.z * xs2[j] + w.w * xs3[j];
        }
        *(float4*)(op + (size_t)c * HW) = make_float4(acc[0], acc[1], acc[2], acc[3]);
    }
}

// ---------------- launch ----------------
extern "C" void kernel_launch(void* const* d_in, const int* in_sizes, int n_in,
                              void* d_out, int out_size) {
    const float* rgb  = (const float*)d_in[0];
    const float* edge = (const float*)d_in[1];
    const float* W1   = (const float*)d_in[2];
    const float* b1   = (const float*)d_in[3];
    const float* Wk1  = (const float*)d_in[4];
    const float* bk1  = (const float*)d_in[5];
    const float* Wk2  = (const float*)d_in[6];
    const float* bk2  = (const float*)d_in[7];
    const float* Wg   = (const float*)d_in[8];
    const float* bg   = (const float*)d_in[9];
    float* out = (float*)d_out;

    reduce_kernel<<<dim3(16, 16), 256>>>(rgb, edge);
    gent_kernel<<<B_, 64>>>(W1, b1, Wk1, bk1, Wg, bg);
    genk_kernel<<<B_ * R_, 256>>>(Wk2, bk2, W1, b1);
    main_kernel<<<dim3(128, B_), 128>>>(rgb, edge, out);
}

// round 5
// speedup vs baseline: 1.1955x; 1.1955x over previous
#include <cuda_runtime.h>
#include <math.h>

#define HW 65536
#define C_ 64
#define R_ 8
#define B_ 4

// ---------------- device scratch (no allocations allowed) ----------------
__device__ float d_partial[16][16];                    // [plane=(b*4+i)][chunk]
__device__ __align__(16) float d_kp4[B_][R_][C_][4];   // folded kernel @ W1
__device__ float d_kb[B_][R_][C_];                     // folded kernel @ b1
__device__ __align__(16) float d_wgp[R_][4];           // Wg @ W1
__device__ float d_bgp[R_];                            // Wg @ b1 + bg

// ---------------- 1) per-plane partial sums (for global means) ----------------
__global__ void reduce_kernel(const float* __restrict__ rgb, const float* __restrict__ edge) {
    int plane = blockIdx.y;             // 0..15  -> b = plane>>2, i = plane&3
    int b = plane >> 2, i = plane & 3;
    const float* src = (i < 3) ? (rgb + (size_t)(b * 3 + i) * HW)
                               : (edge + (size_t)b * HW);
    const float4* p = (const float4*)src + blockIdx.x * 1024;   // 16 chunks of 4096 floats
    int tid = threadIdx.x;              // 256 threads
    float s = 0.f;
#pragma unroll
    for (int k = 0; k < 4; k++) {
        float4 v = p[tid + k * 256];
        s += (v.x + v.y) + (v.z + v.w);
    }
#pragma unroll
    for (int off = 16; off; off >>= 1) s += __shfl_down_sync(0xFFFFFFFFu, s, off);
    __shared__ float ws[8];
    if ((tid & 31) == 0) ws[tid >> 5] = s;
    __syncthreads();
    if (tid < 8) {
        float v = ws[tid];
#pragma unroll
        for (int off = 4; off; off >>= 1) v += __shfl_down_sync(0xFFu, v, off);
        if (tid == 0) d_partial[plane][blockIdx.x] = v;
    }
}

// ---------------- 2) fused setup: means -> g -> t -> generated kernel, folded ----------------
// 32 blocks (b,r), 256 threads. Each block redundantly computes the tiny g/t chain.
__global__ void __launch_bounds__(256) setup_kernel(
        const float* __restrict__ W1, const float* __restrict__ b1,
        const float* __restrict__ Wk1, const float* __restrict__ bk1,
        const float* __restrict__ Wk2, const float* __restrict__ bk2,
        const float* __restrict__ Wg, const float* __restrict__ bg) {
    __shared__ float m4[4], g[64], tg[8];
    __shared__ float kern[4096];                     // kernel[co*64+ci]
    int b = blockIdx.x >> 3, r = blockIdx.x & 7;
    int tid = threadIdx.x;

    if (tid < 4) {
        float s = 0.f;
#pragma unroll
        for (int ch = 0; ch < 16; ch++) s += d_partial[b * 4 + tid][ch];
        m4[tid] = s * (1.0f / 65536.0f);
    }
    __syncthreads();
    if (tid < 64) {
        g[tid] = b1[tid] + W1[tid * 4 + 0] * m4[0] + W1[tid * 4 + 1] * m4[1]
                         + W1[tid * 4 + 2] * m4[2] + W1[tid * 4 + 3] * m4[3];
    }
    __syncthreads();
    if (tid < 8) {
        int row = r * 8 + tid;
        float a = bk1[row];
#pragma unroll 8
        for (int c = 0; c < 64; c++) a += Wk1[row * 64 + c] * g[c];
        tg[tid] = 1.f / (1.f + expf(-a));
    }
    __syncthreads();

    // generated kernel for (b, r): kern[o] = bk2[r][o] + sum_i tg[i]*Wk2[r][o][i]
    const float4* w2 = (const float4*)(Wk2 + (size_t)r * 4096 * 8);
    const float* bk = bk2 + r * 4096;
    float t0 = tg[0], t1 = tg[1], t2 = tg[2], t3 = tg[3];
    float t4 = tg[4], t5 = tg[5], t6 = tg[6], t7 = tg[7];
#pragma unroll
    for (int it = 0; it < 16; it++) {
        int o = tid + it * 256;
        float4 wa = w2[o * 2], wb = w2[o * 2 + 1];
        kern[o] = bk[o] + t0 * wa.x + t1 * wa.y + t2 * wa.z + t3 * wa.w
                        + t4 * wb.x + t5 * wb.y + t6 * wb.z + t7 * wb.w;
    }
    __syncthreads();

    // fold through W1 (64x4) and b1 (64)
    int c = tid >> 2, j = tid & 3;                   // 64 x 4 threads
    float acc = 0.f;
#pragma unroll 8
    for (int ci = 0; ci < 64; ci++) acc += kern[c * 64 + ci] * W1[ci * 4 + j];
    d_kp4[b][r][c][j] = acc;
    if (j == 0) {
        float ab = 0.f;
#pragma unroll 8
        for (int ci = 0; ci < 64; ci++) ab += kern[c * 64 + ci] * b1[ci];
        d_kb[b][r][c] = ab;
    }

    // folded guide weights (once, in block 0)
    if (blockIdx.x == 0) {
        if (tid >= 64 && tid < 96) {
            int rr = (tid - 64) >> 2, jj = tid & 3;
            float s = 0.f;
            for (int cc = 0; cc < 64; cc++) s += Wg[rr * 64 + cc] * W1[cc * 4 + jj];
            d_wgp[rr][jj] = s;
        } else if (tid >= 96 && tid < 104) {
            int rr = tid - 96;
            float s = bg[rr];
            for (int cc = 0; cc < 64; cc++) s += Wg[rr * 64 + cc] * b1[cc];
            d_bgp[rr] = s;
        }
    }
}

// ---------------- 3) streaming main pass: guide argmax + 64x5 matvec ----------------
// 2 pixels/thread, 256 threads/block -> 131072 threads (2x the old occupancy)
__global__ void __launch_bounds__(256) main_kernel(const float* __restrict__ rgb,
                                                   const float* __restrict__ edge,
                                                   float* __restrict__ out) {
    // padded stride 65: LDS.128 start bank = (4r + 4c) mod 32 -> disjoint per region
    __shared__ float4 skp[R_][C_ + 1];
    __shared__ float  skb[R_][C_ + 1];
    int tid = threadIdx.x;
    int b = blockIdx.y;

    const float4* kps = (const float4*)&d_kp4[b][0][0][0];
#pragma unroll
    for (int it = 0; it < 2; it++) {
        int idx = tid + it * 256;
        skp[idx >> 6][idx & 63] = kps[idx];
        skb[idx >> 6][idx & 63] = (&d_kb[b][0][0])[idx];
    }

    float4 wg[8]; float bgr[8];
#pragma unroll
    for (int r = 0; r < 8; r++) {
        wg[r] = *(const float4*)d_wgp[r];
        bgr[r] = d_bgp[r];
    }
    __syncthreads();

    int pb = blockIdx.x * 512 + tid * 2;   // 2 consecutive pixels per thread
    const float* base = rgb + (size_t)b * 3 * HW;
    float2 c0 = *(const float2*)(base + pb);
    float2 c1 = *(const float2*)(base + HW + pb);
    float2 c2 = *(const float2*)(base + 2 * HW + pb);
    float2 c3 = *(const float2*)(edge + (size_t)b * HW + pb);
    float xs0[2] = {c0.x, c0.y};
    float xs1[2] = {c1.x, c1.y};
    float xs2[2] = {c2.x, c2.y};
    float xs3[2] = {c3.x, c3.y};

    int rsel[2];
#pragma unroll
    for (int j = 0; j < 2; j++) {
        float best = -3.4e38f; int ri = 0;
#pragma unroll
        for (int r = 0; r < 8; r++) {
            float gv = bgr[r] + wg[r].x * xs0[j] + wg[r].y * xs1[j]
                              + wg[r].z * xs2[j] + wg[r].w * xs3[j];
            if (gv > best) { best = gv; ri = r; }   // strict > keeps first max (jnp.argmax)
        }
        rsel[j] = ri;
    }

    float* op = out + (size_t)b * 64 * HW + pb;
#pragma unroll 8
    for (int c = 0; c < 64; c++) {
        float acc[2];
#pragma unroll
        for (int j = 0; j < 2; j++) {
            float4 w = skp[rsel[j]][c];
            acc[j] = skb[rsel[j]][c] + w.x * xs0[j] + w.y * xs1[j]
                                     + w.z * xs2[j] + w.w * xs3[j];
        }
        *(float2*)(op + (size_t)c * HW) = make_float2(acc[0], acc[1]);
    }
}

// ---------------- launch ----------------
extern "C" void kernel_launch(void* const* d_in, const int* in_sizes, int n_in,
                              void* d_out, int out_size) {
    const float* rgb  = (const float*)d_in[0];
    const float* edge = (const float*)d_in[1];
    const float* W1   = (const float*)d_in[2];
    const float* b1   = (const float*)d_in[3];
    const float* Wk1  = (const float*)d_in[4];
    const float* bk1  = (const float*)d_in[5];
    const float* Wk2  = (const float*)d_in[6];
    const float* bk2  = (const float*)d_in[7];
    const float* Wg   = (const float*)d_in[8];
    const float* bg   = (const float*)d_in[9];
    float* out = (float*)d_out;

    reduce_kernel<<<dim3(16, 16), 256>>>(rgb, edge);
    setup_kernel<<<B_ * R_, 256>>>(W1, b1, Wk1, bk1, Wk2, bk2, Wg, bg);
    main_kernel<<<dim3(128, B_), 256>>>(rgb, edge, out);
}